// round 5
// baseline (speedup 1.0000x reference)
#include <cuda_runtime.h>

#define TT   512
#define BB   2048
#define NTAG 16
#define LOG2E 1.4426950408889634f

// scratch: h sequence (T, B, 4) fp32 = 16.8 MB
__device__ float g_h[(size_t)TT * BB * 4];

typedef unsigned long long u64;

__device__ __forceinline__ float rcp_ap(float x)  { float r; asm("rcp.approx.f32 %0, %1;"  : "=f"(r) : "f"(x)); return r; }
__device__ __forceinline__ float ex2_ap(float x)  { float r; asm("ex2.approx.f32 %0, %1;"  : "=f"(r) : "f"(x)); return r; }
__device__ __forceinline__ float lg2_ap(float x)  { float r; asm("lg2.approx.f32 %0, %1;"  : "=f"(r) : "f"(x)); return r; }
__device__ __forceinline__ float cos_ap(float x)  { float r; asm("cos.approx.f32 %0, %1;"  : "=f"(r) : "f"(x)); return r; }

// packed f32x2 helpers (sm_100+): one FFMA2 instruction does 2 fp32 fmas
__device__ __forceinline__ u64 pk(float lo, float hi) {
    u64 r; asm("mov.b64 %0, {%1, %2};" : "=l"(r) : "f"(lo), "f"(hi)); return r;
}
__device__ __forceinline__ void upk(u64 v, float& lo, float& hi) {
    asm("mov.b64 {%0, %1}, %2;" : "=f"(lo), "=f"(hi) : "l"(v));
}
__device__ __forceinline__ u64 fma2(u64 a, u64 b, u64 c) {
    u64 d; asm("fma.rn.f32x2 %0, %1, %2, %3;" : "=l"(d) : "l"(a), "l"(b), "l"(c)); return d;
}

// x-part of pre for one gate (4 wires), packed as two f32x2 accumulators.
__device__ __forceinline__ void xacc_packed(
    const float4& A, const float4& B,
    const u64* wxp01, const u64* wxp23, u64 thp01, u64 thp23,
    u64& o01, u64& o23)
{
    float xv[8] = {A.x, A.y, A.z, A.w, B.x, B.y, B.z, B.w};
    u64 p01 = thp01, p23 = thp23;
#pragma unroll
    for (int d = 0; d < 8; d++) {
        u64 xd = pk(xv[d], xv[d]);
        p01 = fma2(xd, wxp01[d], p01);
        p23 = fma2(xd, wxp23[d], p23);
    }
    o01 = p01; o23 = p23;
}

// ---------------------------------------------------------------------------
// Kernel A: LSTM recurrence. 4 lanes per chain (one per gate g).
// Lane g: pre[g][0..3] -> cos -> e-products -> gate nonlinearity (exact
// ex2/rcp formulas). Butterfly 4x4 transpose (4 shfl) gives lane g the
// (F,I,G,O) of wire g; lane g alone computes cx_g, h_g (single-wire combine);
// butterfly allgather (3 shfl) re-broadcasts h0..h3 to all lanes.
// ---------------------------------------------------------------------------
__global__ void __launch_bounds__(32, 1)
recur_kernel(const float* __restrict__ x,
             const float* __restrict__ w_gates,
             const float* __restrict__ b_gates,
             const float* __restrict__ rx_theta)
{
    const int tid = blockIdx.x * 32 + threadIdx.x;   // 0..8191
    const int b   = tid >> 2;                        // chain 0..2047
    const int g   = tid & 3;                         // gate (f,i,g,o)
    const bool hi1 = (g & 1), hi2 = (g & 2);

    // per-lane weights: w_gates layout (4,4,12): [g*48 + k*12 + d]
    float wx[4][8], wh[4][4], th[4];
#pragma unroll
    for (int k = 0; k < 4; k++) {
#pragma unroll
        for (int d = 0; d < 8; d++) wx[k][d] = w_gates[g*48 + k*12 + d];
#pragma unroll
        for (int j = 0; j < 4; j++) wh[k][j] = w_gates[g*48 + k*12 + 8 + j];
        th[k] = b_gates[g*4 + k] + rx_theta[g*4 + k];
    }
    // pack weights for f32x2: pair (k=0,1) and (k=2,3)
    u64 wxp01[8], wxp23[8], whp01[4], whp23[4];
#pragma unroll
    for (int d = 0; d < 8; d++) { wxp01[d] = pk(wx[0][d], wx[1][d]); wxp23[d] = pk(wx[2][d], wx[3][d]); }
#pragma unroll
    for (int j = 0; j < 4; j++) { whp01[j] = pk(wh[0][j], wh[1][j]); whp23[j] = pk(wh[2][j], wh[3][j]); }
    u64 thp01 = pk(th[0], th[1]), thp23 = pk(th[2], th[3]);

    // lane 2 is the tanh gate; lanes 0,1,3 are sigmoid gates
    const float gm = (g == 2) ?  2.0f * LOG2E : -LOG2E;
    const float gA = (g == 2) ? -2.0f         :  1.0f;
    const float gB = (g == 2) ?  1.0f         :  0.0f;

    float h0 = 0.f, h1 = 0.f, h2 = 0.f, h3 = 0.f;
    float cx = 0.f;                                  // only wire g's cell state

    const float4* xp = (const float4*)x;             // (t*BB + b)*2 indexing
    float4 xa[4], xb[4];                             // 4-deep prefetch ring
#pragma unroll
    for (int p = 0; p < 4; p++) {
        size_t i = ((size_t)p * BB + b) * 2;
        xa[p] = xp[i]; xb[p] = xp[i + 1];
    }

    // x-part of pre for t=0 (one step ahead); consumes slot 0, then reload x[4]
    u64 xp01, xp23;
    xacc_packed(xa[0], xb[0], wxp01, wxp23, thp01, thp23, xp01, xp23);
    {
        size_t i4 = ((size_t)4 * BB + b) * 2;
        xa[0] = xp[i4]; xb[0] = xp[i4 + 1];
    }

    float* hout = g_h + (size_t)b * 4 + g;           // own-wire store, stride BB*4

#pragma unroll 4
    for (int t = 0; t < TT; t++) {
        // ---- pre = xacc + Wh·h (packed) ; c = cos(pre)  [h-critical path] ----
        u64 hb0 = pk(h0, h0), hb1 = pk(h1, h1), hb2 = pk(h2, h2), hb3 = pk(h3, h3);
        u64 p01 = fma2(hb0, whp01[0], xp01);
        p01 = fma2(hb1, whp01[1], p01);
        p01 = fma2(hb2, whp01[2], p01);
        p01 = fma2(hb3, whp01[3], p01);
        u64 p23 = fma2(hb0, whp23[0], xp23);
        p23 = fma2(hb1, whp23[1], p23);
        p23 = fma2(hb2, whp23[2], p23);
        p23 = fma2(hb3, whp23[3], p23);
        float pre0, pre1, pre2, pre3;
        upk(p01, pre0, pre1); upk(p23, pre2, pre3);
        float c0 = cos_ap(pre0), c1 = cos_ap(pre1), c2 = cos_ap(pre2), c3 = cos_ap(pre3);

        // ---- off-path: next step's x-part + ring refill ----
        {
            int slot = (t + 1) & 3;
            xacc_packed(xa[slot], xb[slot], wxp01, wxp23, thp01, thp23, xp01, xp23);
            int tp = t + 5; if (tp > TT - 1) tp = TT - 1;
            size_t i = ((size_t)tp * BB + b) * 2;
            xa[slot] = xp[i]; xb[slot] = xp[i + 1];
        }

        // ---- expvals: e0=c1c2c3, e1=c0c1, e2=e1c2, e3=e1t23 ----
        float t23 = c2 * c3;
        float e1  = c0 * c1;
        float e0  = c1 * t23;
        float e2  = e1 * c2;
        float e3  = e1 * t23;

        // ---- gate nonlinearity (exact): v = fma(A, rcp(ex2(m*e)+1), B) ----
        float v0 = fmaf(gA, rcp_ap(ex2_ap(gm * e0) + 1.0f), gB);
        float v1 = fmaf(gA, rcp_ap(ex2_ap(gm * e1) + 1.0f), gB);
        float v2 = fmaf(gA, rcp_ap(ex2_ap(gm * e2) + 1.0f), gB);
        float v3 = fmaf(gA, rcp_ap(ex2_ap(gm * e3) + 1.0f), gB);

        // ---- butterfly 4x4 transpose: lane g ends with column g = (F,I,G,O) of wire g ----
        // stage xor2: swap off-diagonal 2x2 blocks
        float s0 = hi2 ? v0 : v2;
        float s1 = hi2 ? v1 : v3;
        float r0 = __shfl_xor_sync(0xffffffffu, s0, 2);
        float r1 = __shfl_xor_sync(0xffffffffu, s1, 2);
        float a0 = hi2 ? r0 : v0;
        float a1 = hi2 ? r1 : v1;
        float a2 = hi2 ? v2 : r0;
        float a3 = hi2 ? v3 : r1;
        // stage xor1: transpose within 2x2 blocks
        float t0 = hi1 ? a0 : a1;
        float t1 = hi1 ? a2 : a3;
        float q0 = __shfl_xor_sync(0xffffffffu, t0, 1);
        float q1 = __shfl_xor_sync(0xffffffffu, t1, 1);
        float F = hi1 ? q0 : a0;
        float I = hi1 ? a1 : q0;
        float G = hi1 ? q1 : a2;
        float O = hi1 ? a3 : q1;

        // ---- single-wire combine (wire g only) ----
        float nc = fmaf(F, cx, I * G);
        cx = nc;
        // tanh(cx) = 1 - 2/(exp(2cx)+1)
        float E  = ex2_ap(nc * (2.0f * LOG2E));
        float rr = rcp_ap(E + 1.0f);
        float tc = fmaf(-2.0f, rr, 1.0f);
        float h  = O * tc;

        // store own wire's h (warp writes 128B contiguous)
        hout[(size_t)t * (BB * 4)] = h;

        // ---- butterfly allgather of h across the quad (3 shfl) ----
        float hp  = __shfl_xor_sync(0xffffffffu, h, 1);
        float hA0 = hi1 ? hp : h;    // wire 2*g1
        float hA1 = hi1 ? h  : hp;   // wire 2*g1+1
        float sA0 = __shfl_xor_sync(0xffffffffu, hA0, 2);
        float sA1 = __shfl_xor_sync(0xffffffffu, hA1, 2);
        h0 = hi2 ? sA0 : hA0;
        h1 = hi2 ? sA1 : hA1;
        h2 = hi2 ? hA0 : sA0;
        h3 = hi2 ? hA1 : sA1;
    }
}

// ---------------------------------------------------------------------------
// Kernel B: logits + log_softmax, memory/occupancy bound.
// ---------------------------------------------------------------------------
__global__ void __launch_bounds__(256)
out_kernel(const float* __restrict__ w_tag,
           const float* __restrict__ b_tag,
           float* __restrict__ out)
{
    float w[NTAG][4], bt[NTAG];
#pragma unroll
    for (int j = 0; j < NTAG; j++) {
#pragma unroll
        for (int k = 0; k < 4; k++) w[j][k] = w_tag[j*4 + k];
        bt[j] = b_tag[j];
    }

    const int NITEM = TT * BB;                 // 1,048,576 rows
    const int NTH   = gridDim.x * blockDim.x;
    int tid = blockIdx.x * blockDim.x + threadIdx.x;

    const float4* hv4 = (const float4*)g_h;
    float4* o4 = (float4*)out;

    for (int it = tid; it < NITEM; it += NTH) {
        float4 hv = hv4[it];
        float lg[NTAG];
#pragma unroll
        for (int j = 0; j < NTAG; j++) {
            lg[j] = fmaf(w[j][3], hv.w,
                    fmaf(w[j][2], hv.z,
                    fmaf(w[j][1], hv.y,
                    fmaf(w[j][0], hv.x, bt[j]))));
        }
        float m = lg[0];
#pragma unroll
        for (int j = 1; j < NTAG; j++) m = fmaxf(m, lg[j]);
        float s = 0.f;
#pragma unroll
        for (int j = 0; j < NTAG; j++)
            s += ex2_ap((lg[j] - m) * LOG2E);
        float ls = fmaf(lg2_ap(s), 0.6931471805599453f, m);
#pragma unroll
        for (int j = 0; j < NTAG; j += 4) {
            o4[(size_t)it * 4 + (j >> 2)] =
                make_float4(lg[j] - ls, lg[j+1] - ls, lg[j+2] - ls, lg[j+3] - ls);
        }
    }
}

extern "C" void kernel_launch(void* const* d_in, const int* in_sizes, int n_in,
                              void* d_out, int out_size)
{
    const float* x        = (const float*)d_in[0];
    const float* w_gates  = (const float*)d_in[1];
    const float* b_gates  = (const float*)d_in[2];
    const float* rx_theta = (const float*)d_in[3];
    const float* w_tag    = (const float*)d_in[4];
    const float* b_tag    = (const float*)d_in[5];

    recur_kernel<<<256, 32>>>(x, w_gates, b_gates, rx_theta);   // 8192 threads
    out_kernel<<<1024, 256>>>(w_tag, b_tag, (float*)d_out);     // 262144 threads
}